// round 15
// baseline (speedup 1.0000x reference)
#include <cuda_runtime.h>

#define Lf 16
#define Cc 64
#define Hh 128
#define Ww 128
#define HW (Hh*Ww)
#define CHW (Cc*HW)
#define LCHW (Lf*CHW)

// -------- scratch (static device globals) --------
__device__ float g_G[(size_t)Lf*25*HW]; // per-tap GEMV planes (26MB)
__device__ float g_B[Lf*HW];           // pre-softmax scores
__device__ float g_q[Lf*HW];           // softmax probs * rstd_j
__device__ float g_mm[HW];             // sum_j p_j * mu_j * rstd_j
__device__ float g_hbar[CHW];          // weighted-avg LN'd features
__device__ float g_attn[CHW];          // attention output (frame-independent)
__device__ float g_stats[2*Lf];        // per-frame mean, rstd
__device__ float g_part[Lf*256*2];     // LN partial sums
__device__ float g_Wfk[Cc*25];         // folded conv weights
__device__ float g_bw[25];             // folded conv bias taps

// -------- packed fp32x2 helpers --------
__device__ __forceinline__ void fma2(unsigned long long &d, unsigned long long a, unsigned long long b) {
    asm("fma.rn.f32x2 %0, %1, %2, %0;" : "+l"(d) : "l"(a), "l"(b));
}
__device__ __forceinline__ unsigned long long pk(float lo, float hi) {
    unsigned long long d;
    asm("mov.b64 %0, {%1,%2};" : "=l"(d) : "f"(lo), "f"(hi));
    return d;
}
__device__ __forceinline__ void upk(float &lo, float &hi, unsigned long long d) {
    asm("mov.b64 {%0,%1}, %2;" : "=f"(lo), "=f"(hi) : "l"(d));
}

// -------- tf32 mma.sync helpers --------
__device__ __forceinline__ unsigned tf32c(float x) {
    unsigned r;
    asm("cvt.rna.tf32.f32 %0, %1;" : "=r"(r) : "f"(x));
    return r;
}
__device__ __forceinline__ void mma_tf32(float &d0, float &d1, float &d2, float &d3,
        unsigned a0, unsigned a1, unsigned a2, unsigned a3, unsigned b0, unsigned b1) {
    asm("mma.sync.aligned.m16n8k8.row.col.f32.tf32.tf32.f32 "
        "{%0,%1,%2,%3}, {%4,%5,%6,%7}, {%8,%9}, {%0,%1,%2,%3};"
        : "+f"(d0), "+f"(d1), "+f"(d2), "+f"(d3)
        : "r"(a0), "r"(a1), "r"(a2), "r"(a3), "r"(b0), "r"(b1));
}

// -------- block reduce (256 threads) -> g_part[(l*256+chunk)*2] --------
__device__ __forceinline__ void reduce_write(float s, float s2, int l, int chunk) {
    #pragma unroll
    for (int o = 16; o > 0; o >>= 1) {
        s  += __shfl_down_sync(0xffffffffu, s,  o);
        s2 += __shfl_down_sync(0xffffffffu, s2, o);
    }
    __shared__ float sh[8], sh2[8];
    int w = threadIdx.x >> 5, lane = threadIdx.x & 31;
    if (lane == 0) { sh[w] = s; sh2[w] = s2; }
    __syncthreads();
    if (w == 0 && lane < 8) {
        s = sh[lane]; s2 = sh2[lane];
        #pragma unroll
        for (int o = 4; o > 0; o >>= 1) {
            s  += __shfl_down_sync(0xffu, s,  o);
            s2 += __shfl_down_sync(0xffu, s2, o);
        }
        if (lane == 0) {
            g_part[(l*256 + chunk)*2]     = s;
            g_part[(l*256 + chunk)*2 + 1] = s2;
        }
    }
}

// ---------------- LN1 partials for layer 0 (reads input directly; no copy) ----------------
__global__ void stats_k(const float* __restrict__ xin) {
    int l = blockIdx.y, chunk = blockIdx.x;
    const float4* src = reinterpret_cast<const float4*>(xin + (size_t)l*CHW) + chunk*2048;
    float s = 0.f, s2 = 0.f;
    #pragma unroll 4
    for (int i = threadIdx.x; i < 2048; i += 256) {
        float4 v = src[i];
        s  += v.x + v.y + v.z + v.w;
        s2 += v.x*v.x + v.y*v.y + v.z*v.z + v.w*v.w;
    }
    reduce_write(s, s2, l, chunk);
}

// ---------------- LN finalize over nchunks (+ optional conv-weight fold) ----------------
__global__ void ln_final_k(const float* __restrict__ Wa_d,
                           const float* __restrict__ Wk_d,
                           const float* __restrict__ bk_d,
                           int do_fold, int nchunks) {
    int w = threadIdx.x >> 5, lane = threadIdx.x & 31;
    float s = 0.f, s2 = 0.f;
    for (int t = lane; t < nchunks; t += 32) {
        s  += g_part[(w*256 + t)*2];
        s2 += g_part[(w*256 + t)*2 + 1];
    }
    #pragma unroll
    for (int o = 16; o > 0; o >>= 1) {
        s  += __shfl_down_sync(0xffffffffu, s,  o);
        s2 += __shfl_down_sync(0xffffffffu, s2, o);
    }
    if (lane == 0) {
        float mu  = s / (float)CHW;
        float var = s2 / (float)CHW - mu*mu;
        g_stats[w*2]     = mu;
        g_stats[w*2 + 1] = rsqrtf(var + 1e-5f);
    }
    if (do_fold) {
        for (int idx = threadIdx.x; idx < Cc*25 + 25; idx += blockDim.x) {
            if (idx < Cc*25) {
                int c = idx / 25, t = idx % 25;
                float acc = 0.f;
                for (int ci = 0; ci < Cc; ci++)
                    acc += Wa_d[(Cc + ci)*25 + t] * Wk_d[ci*Cc + c];
                g_Wfk[idx] = acc;
            } else {
                int t = idx - Cc*25;
                float acc = 0.f;
                for (int ci = 0; ci < Cc; ci++)
                    acc += Wa_d[(Cc + ci)*25 + t] * bk_d[ci];
                g_bw[t] = acc;
            }
        }
    }
}

// ---------------- G[t,p] = sum_c Wfk[c,t] * LN1(x)[c,p]  (per-pixel 25-out GEMV, 2px/thr) ----------------
// grid (HW/512, Lf), 256 threads
__global__ void __launch_bounds__(256) g_gemv_k(const float* __restrict__ xbase,
        const float* __restrict__ gg, const float* __restrict__ bb) {
    __shared__ __align__(16) unsigned long long Wp[Cc*14]; // Wp[c][k]=(Wfk[c,2k],Wfk[c,2k+1]); k=0..12
    int tid = threadIdx.x;
    for (int i = tid; i < Cc*13; i += 256) {
        int c = i / 13, k = i - c*13;
        float w0 = g_Wfk[c*25 + 2*k];
        float w1 = (2*k + 1 < 25) ? g_Wfk[c*25 + 2*k + 1] : 0.f;
        Wp[c*14 + k] = pk(w0, w1);
    }
    __syncthreads();
    int l = blockIdx.y;
    int p = blockIdx.x*512 + tid;
    float mu = g_stats[l*2], rs = g_stats[l*2 + 1];
    const float* xl = xbase + (size_t)l*CHW;

    unsigned long long a0[13], a1[13];
    #pragma unroll
    for (int k = 0; k < 13; k++) { a0[k] = 0ull; a1[k] = 0ull; }
    for (int c = 0; c < Cc; c++) {
        int off = c*HW + p;
        float h0 = (xl[off]     - mu)*rs*gg[off]     + bb[off];
        float h1 = (xl[off+256] - mu)*rs*gg[off+256] + bb[off+256];
        unsigned long long hd0 = pk(h0, h0), hd1 = pk(h1, h1);
        const ulonglong2* wr = reinterpret_cast<const ulonglong2*>(&Wp[c*14]);
        #pragma unroll
        for (int k2 = 0; k2 < 6; k2++) {
            ulonglong2 w = wr[k2];
            fma2(a0[2*k2],   w.x, hd0); fma2(a1[2*k2],   w.x, hd1);
            fma2(a0[2*k2+1], w.y, hd0); fma2(a1[2*k2+1], w.y, hd1);
        }
        unsigned long long w12 = Wp[c*14 + 12];
        fma2(a0[12], w12, hd0);
        fma2(a1[12], w12, hd1);
    }
    float* Gl = g_G + (size_t)l*25*HW;
    #pragma unroll
    for (int k = 0; k < 13; k++) {
        float lo, hi;
        upk(lo, hi, a0[k]);
        Gl[(2*k)*HW + p] = lo;
        if (2*k + 1 < 25) Gl[(2*k+1)*HW + p] = hi;
        upk(lo, hi, a1[k]);
        Gl[(2*k)*HW + p + 256] = lo;
        if (2*k + 1 < 25) Gl[(2*k+1)*HW + p + 256] = hi;
    }
}

// ---------------- B[p] = sum_t G[t, p+shift_t] + border bias ----------------
__global__ void __launch_bounds__(256) stencil_k() {
    __shared__ float bwS[25];
    int tid = threadIdx.x;
    if (tid < 25) bwS[tid] = g_bw[tid];
    __syncthreads();
    int l = blockIdx.y;
    int p = blockIdx.x*256 + tid;
    int y = p >> 7, xx0 = p & 127;
    const float* Gl = g_G + (size_t)l*25*HW;
    float acc = 0.f;
    #pragma unroll
    for (int ky = 0; ky < 5; ky++) {
        int yy = y + ky - 2;
        bool yok = (yy >= 0 && yy < Hh);
        #pragma unroll
        for (int kx = 0; kx < 5; kx++) {
            int xc = xx0 + kx - 2;
            if (yok && xc >= 0 && xc < Ww) {
                int t = ky*5 + kx;
                acc += Gl[t*HW + yy*Ww + xc] + bwS[t];
            }
        }
    }
    g_B[l*HW + p] = acc;
}

// ---------------- softmax over frames -> q[j,p], mm[p] ----------------
__global__ void softmax_k() {
    int p = blockIdx.x*256 + threadIdx.x;
    float v[Lf]; float m = -1e30f;
    #pragma unroll
    for (int j = 0; j < Lf; j++) { v[j] = g_B[j*HW + p]; m = fmaxf(m, v[j]); }
    float ssum = 0.f;
    #pragma unroll
    for (int j = 0; j < Lf; j++) { v[j] = expf(v[j] - m); ssum += v[j]; }
    float inv = 1.f / ssum;
    float mm = 0.f;
    #pragma unroll
    for (int j = 0; j < Lf; j++) {
        float pj = v[j] * inv;
        float rs = g_stats[j*2 + 1], mu = g_stats[j*2];
        g_q[j*HW + p] = pj * rs;
        mm += pj * mu * rs;
    }
    g_mm[p] = mm;
}

// ---------------- hbar[c,p] ----------------
__global__ void __launch_bounds__(256) hbar_k(const float* __restrict__ xbase,
        const float* __restrict__ gg, const float* __restrict__ bb) {
    int c = blockIdx.y;
    int p = (blockIdx.x*256 + threadIdx.x) * 4;
    float4 mm4 = *reinterpret_cast<const float4*>(g_mm + p);
    float4 a = make_float4(-mm4.x, -mm4.y, -mm4.z, -mm4.w);
    #pragma unroll
    for (int j = 0; j < Lf; j++) {
        float4 xv = *reinterpret_cast<const float4*>(xbase + (size_t)j*CHW + c*HW + p);
        float4 qv = *reinterpret_cast<const float4*>(g_q + j*HW + p);
        a.x += qv.x*xv.x; a.y += qv.y*xv.y; a.z += qv.z*xv.z; a.w += qv.w*xv.w;
    }
    float4 g4 = *reinterpret_cast<const float4*>(gg + c*HW + p);
    float4 b4 = *reinterpret_cast<const float4*>(bb + c*HW + p);
    a.x = a.x*g4.x + b4.x; a.y = a.y*g4.y + b4.y;
    a.z = a.z*g4.z + b4.z; a.w = a.w*g4.w + b4.w;
    *reinterpret_cast<float4*>(g_hbar + c*HW + p) = a;
}

// ---------------- attn = Wv * hbar + bv ----------------
__global__ void __launch_bounds__(128) attn_gemv_k(const float* __restrict__ Wv,
                                                   const float* __restrict__ bv) {
    __shared__ __align__(16) unsigned long long Wp[Cc*32];
    int tid = threadIdx.x;
    for (int i = tid; i < Cc*32; i += 128) {
        int c = i >> 5, k = i & 31;
        Wp[c*32 + k] = pk(Wv[(2*k)*Cc + c], Wv[(2*k+1)*Cc + c]);
    }
    __syncthreads();
    int p = blockIdx.x*128 + tid;
    unsigned long long acc2[32];
    #pragma unroll
    for (int k = 0; k < 32; k++) acc2[k] = pk(bv[2*k], bv[2*k+1]);
    for (int c = 0; c < Cc; c++) {
        float h = g_hbar[c*HW + p];
        unsigned long long hd = pk(h, h);
        const ulonglong2* wr = reinterpret_cast<const ulonglong2*>(&Wp[c*32]);
        #pragma unroll
        for (int k2 = 0; k2 < 16; k2++) {
            ulonglong2 w = wr[k2];
            fma2(acc2[2*k2],   w.x, hd);
            fma2(acc2[2*k2+1], w.y, hd);
        }
    }
    #pragma unroll
    for (int k = 0; k < 32; k++) {
        float lo, hi;
        upk(lo, hi, acc2[k]);
        g_attn[(2*k)*HW + p]   = lo;
        g_attn[(2*k+1)*HW + p] = hi;
    }
}

// ---------------- x = xsrc + attn (all frames) + LN2 partials (fused copy for layer 0) ----------------
__global__ void addres_k(float* __restrict__ x, const float* __restrict__ xsrc) {
    int l = blockIdx.y, chunk = blockIdx.x;
    const float4* at = reinterpret_cast<const float4*>(g_attn) + chunk*2048;
    const float4* xs = reinterpret_cast<const float4*>(xsrc + (size_t)l*CHW) + chunk*2048;
    float4* xd = reinterpret_cast<float4*>(x + (size_t)l*CHW) + chunk*2048;
    float s = 0.f, s2 = 0.f;
    #pragma unroll 4
    for (int i = threadIdx.x; i < 2048; i += 256) {
        float4 v = xs[i];
        float4 a = at[i];
        v.x += a.x; v.y += a.y; v.z += a.z; v.w += a.w;
        xd[i] = v;
        s  += v.x + v.y + v.z + v.w;
        s2 += v.x*v.x + v.y*v.y + v.z*v.z + v.w*v.w;
    }
    reduce_write(s, s2, l, chunk);
}

// ---------------- tensor-core FFN (tf32 mma.sync), 2 CTAs/SM ----------------
#define FFN_SMEM (26112*4)

__global__ void __launch_bounds__(256, 2) ffn_k(float* __restrict__ x,
        const float* __restrict__ gg, const float* __restrict__ bb,
        const float* __restrict__ W1, const float* __restrict__ b1,
        const float* __restrict__ W2, const float* __restrict__ b2) {
    extern __shared__ __align__(16) float smf[];
    unsigned* hsu = reinterpret_cast<unsigned*>(smf);
    unsigned* w1u = reinterpret_cast<unsigned*>(smf + 8704);
    unsigned* f1u = reinterpret_cast<unsigned*>(smf);          // phase2 alias of A
    unsigned* w2u = reinterpret_cast<unsigned*>(smf + 17408);  // region B
    float*    ob  = smf + 17408;                                // phase3 alias of B
    __shared__ float b1s[128];
    __shared__ float b2s[64];

    int tid = threadIdx.x;
    int l = blockIdx.y;
    int p0 = blockIdx.x * 128;
    float mu = g_stats[l*2], rs = g_stats[l*2 + 1];
    float* xl = x + (size_t)l*CHW;

    if (tid < 128) b1s[tid] = b1[tid];
    if (tid < 64)  b2s[tid] = b2[tid];

    for (int i = tid; i < 2048; i += 256) {
        int c = i >> 5, px4 = (i & 31) * 4;
        int off = c*HW + p0 + px4;
        float4 xv = *reinterpret_cast<const float4*>(xl + off);
        float4 g4 = *reinterpret_cast<const float4*>(gg + off);
        float4 b4 = *reinterpret_cast<const float4*>(bb + off);
        float hv[4];
        hv[0] = (xv.x - mu)*rs*g4.x + b4.x;
        hv[1] = (xv.y - mu)*rs*g4.y + b4.y;
        hv[2] = (xv.z - mu)*rs*g4.z + b4.z;
        hv[3] = (xv.w - mu)*rs*g4.w + b4.w;
        #pragma unroll
        for (int u = 0; u < 4; u++)
            hsu[(px4+u)*68 + c] = tf32c(hv[u]);
    }
    for (int i = tid; i < 2048; i += 256) {
        int o = i >> 4, c4 = (i & 15) * 4;
        float4 w4 = *reinterpret_cast<const float4*>(W1 + o*64 + c4);
        uint4 t;
        t.x = tf32c(w4.x); t.y = tf32c(w4.y); t.z = tf32c(w4.z); t.w = tf32c(w4.w);
        *reinterpret_cast<uint4*>(w1u + o*68 + c4) = t;
    }
    for (int i = tid; i < 2048; i += 256) {
        int c = i >> 5, o4 = (i & 31) * 4;
        float4 w4 = *reinterpret_cast<const float4*>(W2 + c*128 + o4);
        uint4 t;
        t.x = tf32c(w4.x); t.y = tf32c(w4.y); t.z = tf32c(w4.z); t.w = tf32c(w4.w);
        *reinterpret_cast<uint4*>(w2u + c*132 + o4) = t;
    }
    __syncthreads();

    int lane = tid & 31, warp = tid >> 5;
    int gid = lane >> 2, tig = lane & 3;
    int m0 = warp * 16;

    float d[16][4];
    #pragma unroll
    for (int nt = 0; nt < 16; nt++) { d[nt][0]=0.f; d[nt][1]=0.f; d[nt][2]=0.f; d[nt][3]=0.f; }
    #pragma unroll
    for (int kt = 0; kt < 8; kt++) {
        int ka = kt*8 + tig;
        unsigned a0 = hsu[(m0+gid)*68 + ka];
        unsigned a1 = hsu[(m0+gid+8)*68 + ka];
        unsigned a2 = hsu[(m0+gid)*68 + ka + 4];
        unsigned a3 = hsu[(m0+gid+8)*68 + ka + 4];
        #pragma unroll
        for (int nt = 0; nt < 16; nt++) {
            unsigned b0 = w1u[(nt*8+gid)*68 + ka];
            unsigned b1f = w1u[(nt*8+gid)*68 + ka + 4];
            mma_tf32(d[nt][0], d[nt][1], d[nt][2], d[nt][3], a0, a1, a2, a3, b0, b1f);
        }
    }
    __syncthreads();

    #pragma unroll
    for (int nt = 0; nt < 16; nt++) {
        int col = nt*8 + 2*tig;
        float v0 = d[nt][0] + b1s[col];
        float v1 = d[nt][1] + b1s[col+1];
        float v2 = d[nt][2] + b1s[col];
        float v3 = d[nt][3] + b1s[col+1];
        v0 = v0 > 0.f ? v0 : 0.01f*v0;
        v1 = v1 > 0.f ? v1 : 0.01f*v1;
        v2 = v2 > 0.f ? v2 : 0.01f*v2;
        v3 = v3 > 0.f ? v3 : 0.01f*v3;
        uint2 lo; lo.x = tf32c(v0); lo.y = tf32c(v1);
        uint2 hi; hi.x = tf32c(v2); hi.y = tf32c(v3);
        *reinterpret_cast<uint2*>(f1u + (m0+gid)*132 + col)   = lo;
        *reinterpret_cast<uint2*>(f1u + (m0+gid+8)*132 + col) = hi;
    }
    __syncthreads();

    float e[8][4];
    #pragma unroll
    for (int nt = 0; nt < 8; nt++) { e[nt][0]=0.f; e[nt][1]=0.f; e[nt][2]=0.f; e[nt][3]=0.f; }
    #pragma unroll
    for (int kt = 0; kt < 16; kt++) {
        int ka = kt*8 + tig;
        unsigned a0 = f1u[(m0+gid)*132 + ka];
        unsigned a1 = f1u[(m0+gid+8)*132 + ka];
        unsigned a2 = f1u[(m0+gid)*132 + ka + 4];
        unsigned a3 = f1u[(m0+gid+8)*132 + ka + 4];
        #pragma unroll
        for (int nt = 0; nt < 8; nt++) {
            unsigned b0 = w2u[(nt*8+gid)*132 + ka];
            unsigned b1f = w2u[(nt*8+gid)*132 + ka + 4];
            mma_tf32(e[nt][0], e[nt][1], e[nt][2], e[nt][3], a0, a1, a2, a3, b0, b1f);
        }
    }
    __syncthreads();

    #pragma unroll
    for (int nt = 0; nt < 8; nt++) {
        int col = nt*8 + 2*tig;
        float2 lo, hi;
        lo.x = e[nt][0] + b2s[col];
        lo.y = e[nt][1] + b2s[col+1];
        hi.x = e[nt][2] + b2s[col];
        hi.y = e[nt][3] + b2s[col+1];
        *reinterpret_cast<float2*>(ob + (m0+gid)*68 + col)   = lo;
        *reinterpret_cast<float2*>(ob + (m0+gid+8)*68 + col) = hi;
    }
    __syncthreads();

    {
        int px = tid & 127;
        int ch0 = (tid >> 7) * 32;
        float s = 0.f, s2 = 0.f;
        #pragma unroll 4
        for (int c = ch0; c < ch0 + 32; c++) {
            int off = c*HW + p0 + px;
            float v = xl[off] + ob[px*68 + c];
            xl[off] = v;
            s += v;
            s2 += v*v;
        }
        reduce_write(s, s2, l, blockIdx.x);
    }
}

// ---------------- launch ----------------
extern "C" void kernel_launch(void* const* d_in, const int* in_sizes, int n_in,
                              void* d_out, int out_size) {
    const float* x_in = (const float*)d_in[0];
    const float* ln1g = (const float*)d_in[1];
    const float* ln1b = (const float*)d_in[2];
    // d_in[3]=Wq, d_in[4]=bq, d_in[10]=ba: dead (softmax over j cancels them)
    const float* Wk   = (const float*)d_in[5];
    const float* bk   = (const float*)d_in[6];
    const float* Wv   = (const float*)d_in[7];
    const float* bv   = (const float*)d_in[8];
    const float* Wa   = (const float*)d_in[9];
    const float* ln2g = (const float*)d_in[11];
    const float* ln2b = (const float*)d_in[12];
    const float* W1   = (const float*)d_in[13];
    const float* b1   = (const float*)d_in[14];
    const float* W2   = (const float*)d_in[15];
    const float* b2   = (const float*)d_in[16];
    float* x = (float*)d_out;

    cudaFuncSetAttribute(ffn_k, cudaFuncAttributeMaxDynamicSharedMemorySize, FFN_SMEM);

    stats_k<<<dim3(128, Lf), 256>>>(x_in);   // layer-0 LN1 partials, no copy

    for (int d = 0; d < 4; d++) {
        const float* xbase = (d == 0) ? x_in : x;   // attention path reads pre-residual tensor
        ln_final_k<<<1, 512>>>(Wa + (size_t)d*2*Cc*25, Wk + (size_t)d*Cc*Cc,
                               bk + (size_t)d*Cc, 1, 128);
        g_gemv_k<<<dim3(HW/512, Lf), 256>>>(xbase, ln1g + (size_t)d*CHW, ln1b + (size_t)d*CHW);
        stencil_k<<<dim3(HW/256, Lf), 256>>>();
        softmax_k<<<HW/256, 256>>>();
        hbar_k<<<dim3(HW/1024, Cc), 256>>>(xbase, ln1g + (size_t)d*CHW, ln1b + (size_t)d*CHW);
        attn_gemv_k<<<HW/128, 128>>>(Wv + (size_t)d*Cc*Cc, bv + (size_t)d*Cc);
        addres_k<<<dim3(128, Lf), 256>>>(x, xbase);
        ln_final_k<<<1, 512>>>(Wa, Wk, bk, 0, 128);
        ffn_k<<<dim3(HW/128, Lf), 256, FFN_SMEM>>>(x, ln2g + (size_t)d*CHW, ln2b + (size_t)d*CHW,
                                                   W1 + (size_t)d*2*Cc*Cc, b1 + (size_t)d*2*Cc,
                                                   W2 + (size_t)d*Cc*2*Cc, b2 + (size_t)d*Cc);
    }
}

// round 17
// speedup vs baseline: 1.4282x; 1.4282x over previous
#include <cuda_runtime.h>

#define Lf 16
#define Cc 64
#define Hh 128
#define Ww 128
#define HW (Hh*Ww)
#define CHW (Cc*HW)
#define LCHW (Lf*CHW)

// -------- scratch (static device globals) --------
__device__ float g_Bpart[8][Lf*HW]; // partial pre-softmax scores (per channel group)
__device__ float g_q[Lf*HW];       // softmax probs * rstd_j
__device__ float g_mm[HW];         // sum_j p_j * mu_j * rstd_j
__device__ float g_hbar[CHW];      // weighted-avg LN'd features
__device__ float g_attn[CHW];      // attention output (frame-independent)
__device__ float g_stats[2*Lf];    // per-frame mean, rstd
__device__ float g_part[Lf*256*2]; // LN partial sums
__device__ float g_Wfk[Cc*25];     // folded conv weights
__device__ float g_bw[25];         // folded conv bias taps

// -------- packed fp32x2 helpers --------
__device__ __forceinline__ void fma2(unsigned long long &d, unsigned long long a, unsigned long long b) {
    asm("fma.rn.f32x2 %0, %1, %2, %0;" : "+l"(d) : "l"(a), "l"(b));
}
__device__ __forceinline__ unsigned long long pk(float lo, float hi) {
    unsigned long long d;
    asm("mov.b64 %0, {%1,%2};" : "=l"(d) : "f"(lo), "f"(hi));
    return d;
}
__device__ __forceinline__ void upk(float &lo, float &hi, unsigned long long d) {
    asm("mov.b64 {%0,%1}, %2;" : "=f"(lo), "=f"(hi) : "l"(d));
}

// -------- tf32 mma.sync helpers --------
__device__ __forceinline__ unsigned tf32c(float x) {
    unsigned r;
    asm("cvt.rna.tf32.f32 %0, %1;" : "=r"(r) : "f"(x));
    return r;
}
__device__ __forceinline__ void mma_tf32(float &d0, float &d1, float &d2, float &d3,
        unsigned a0, unsigned a1, unsigned a2, unsigned a3, unsigned b0, unsigned b1) {
    asm("mma.sync.aligned.m16n8k8.row.col.f32.tf32.tf32.f32 "
        "{%0,%1,%2,%3}, {%4,%5,%6,%7}, {%8,%9}, {%0,%1,%2,%3};"
        : "+f"(d0), "+f"(d1), "+f"(d2), "+f"(d3)
        : "r"(a0), "r"(a1), "r"(a2), "r"(a3), "r"(b0), "r"(b1));
}

// -------- block reduce (256 threads) -> g_part[(l*256+chunk)*2] --------
__device__ __forceinline__ void reduce_write(float s, float s2, int l, int chunk) {
    #pragma unroll
    for (int o = 16; o > 0; o >>= 1) {
        s  += __shfl_down_sync(0xffffffffu, s,  o);
        s2 += __shfl_down_sync(0xffffffffu, s2, o);
    }
    __shared__ float sh[8], sh2[8];
    int w = threadIdx.x >> 5, lane = threadIdx.x & 31;
    if (lane == 0) { sh[w] = s; sh2[w] = s2; }
    __syncthreads();
    if (w == 0 && lane < 8) {
        s = sh[lane]; s2 = sh2[lane];
        #pragma unroll
        for (int o = 4; o > 0; o >>= 1) {
            s  += __shfl_down_sync(0xffu, s,  o);
            s2 += __shfl_down_sync(0xffu, s2, o);
        }
        if (lane == 0) {
            g_part[(l*256 + chunk)*2]     = s;
            g_part[(l*256 + chunk)*2 + 1] = s2;
        }
    }
}

// ---------------- LN1 partials for layer 0 (reads input directly; no copy) ----------------
__global__ void stats_k(const float* __restrict__ xin) {
    int l = blockIdx.y, chunk = blockIdx.x;
    const float4* src = reinterpret_cast<const float4*>(xin + (size_t)l*CHW) + chunk*2048;
    float s = 0.f, s2 = 0.f;
    #pragma unroll 4
    for (int i = threadIdx.x; i < 2048; i += 256) {
        float4 v = src[i];
        s  += v.x + v.y + v.z + v.w;
        s2 += v.x*v.x + v.y*v.y + v.z*v.z + v.w*v.w;
    }
    reduce_write(s, s2, l, chunk);
}

// ---------------- LN finalize over nchunks (+ optional conv-weight fold) ----------------
__global__ void ln_final_k(const float* __restrict__ Wa_d,
                           const float* __restrict__ Wk_d,
                           const float* __restrict__ bk_d,
                           int do_fold, int nchunks) {
    int w = threadIdx.x >> 5, lane = threadIdx.x & 31;
    float s = 0.f, s2 = 0.f;
    for (int t = lane; t < nchunks; t += 32) {
        s  += g_part[(w*256 + t)*2];
        s2 += g_part[(w*256 + t)*2 + 1];
    }
    #pragma unroll
    for (int o = 16; o > 0; o >>= 1) {
        s  += __shfl_down_sync(0xffffffffu, s,  o);
        s2 += __shfl_down_sync(0xffffffffu, s2, o);
    }
    if (lane == 0) {
        float mu  = s / (float)CHW;
        float var = s2 / (float)CHW - mu*mu;
        g_stats[w*2]     = mu;
        g_stats[w*2 + 1] = rsqrtf(var + 1e-5f);
    }
    if (do_fold) {
        for (int idx = threadIdx.x; idx < Cc*25 + 25; idx += blockDim.x) {
            if (idx < Cc*25) {
                int c = idx / 25, t = idx % 25;
                float acc = 0.f;
                for (int ci = 0; ci < Cc; ci++)
                    acc += Wa_d[(Cc + ci)*25 + t] * Wk_d[ci*Cc + c];
                g_Wfk[idx] = acc;
            } else {
                int t = idx - Cc*25;
                float acc = 0.f;
                for (int ci = 0; ci < Cc; ci++)
                    acc += Wa_d[(Cc + ci)*25 + t] * bk_d[ci];
                g_bw[t] = acc;
            }
        }
    }
}

// ---------------- Bpart[cg] = conv5(LN1(x)[8ch group], Wfk) (+ border bias on cg0) ----------------
__global__ void __launch_bounds__(256) conv_b_k(const float* __restrict__ x,
        const float* __restrict__ gg, const float* __restrict__ bb) {
    __shared__ __align__(16) float tile[4][12*132];
    __shared__ float wf[8*25];
    __shared__ float bwS[25];
    int tid = threadIdx.x;
    int cg = blockIdx.x;
    int cbase = cg * 8;
    for (int i = tid; i < 8*25; i += 256) wf[i] = g_Wfk[cbase*25 + i];
    if (tid < 25) bwS[tid] = g_bw[tid];
    int l = blockIdx.z;
    int y0 = blockIdx.y * 8;
    float mu = g_stats[l*2], rs = g_stats[l*2 + 1];
    const float* xl = x + (size_t)l*CHW;
    int tx = tid & 31, ty = tid >> 5;
    float acc[4] = {0.f, 0.f, 0.f, 0.f};

    for (int c0 = 0; c0 < 8; c0 += 4) {
        __syncthreads();
        #pragma unroll 4
        for (int i = tid; i < 4*1584; i += 256) {
            int cc = i / 1584;
            int rem = i - cc*1584;
            int r = rem / 132, col = rem - r*132;
            int yy = y0 + r - 2, xx = col - 2;
            float v = 0.f;
            if (yy >= 0 && yy < Hh && xx >= 0 && xx < Ww) {
                int off = (cbase + c0 + cc)*HW + yy*Ww + xx;
                v = (xl[off] - mu)*rs*gg[off] + bb[off];
            }
            tile[cc][rem] = v;
        }
        __syncthreads();
        #pragma unroll
        for (int cc = 0; cc < 4; cc++) {
            const float* wr = &wf[(c0+cc)*25];
            #pragma unroll
            for (int ky = 0; ky < 5; ky++) {
                const float* rowp = &tile[cc][(ty+ky)*132 + tx*4];
                float4 v0 = *reinterpret_cast<const float4*>(rowp);
                float4 v1 = *reinterpret_cast<const float4*>(rowp + 4);
                float vals[8] = {v0.x, v0.y, v0.z, v0.w, v1.x, v1.y, v1.z, v1.w};
                #pragma unroll
                for (int kx = 0; kx < 5; kx++) {
                    float w = wr[ky*5 + kx];
                    acc[0] += w * vals[kx];
                    acc[1] += w * vals[kx+1];
                    acc[2] += w * vals[kx+2];
                    acc[3] += w * vals[kx+3];
                }
            }
        }
    }
    int py = y0 + ty;
    #pragma unroll
    for (int ox = 0; ox < 4; ox++) {
        int px = tx*4 + ox;
        float bias = 0.f;
        if (cg == 0) {
            #pragma unroll
            for (int ky = 0; ky < 5; ky++)
                #pragma unroll
                for (int kx = 0; kx < 5; kx++) {
                    int yy = py + ky - 2, xx = px + kx - 2;
                    if (yy >= 0 && yy < Hh && xx >= 0 && xx < Ww) bias += bwS[ky*5 + kx];
                }
        }
        g_Bpart[cg][l*HW + py*Ww + px] = acc[ox] + bias;
    }
}

// ---------------- softmax over frames (sums 8 conv partials) -> q[j,p], mm[p] ----------------
__global__ void softmax_k() {
    int p = blockIdx.x*256 + threadIdx.x;
    float v[Lf]; float m = -1e30f;
    #pragma unroll
    for (int j = 0; j < Lf; j++) {
        float b = 0.f;
        #pragma unroll
        for (int gidx = 0; gidx < 8; gidx++) b += g_Bpart[gidx][j*HW + p];
        v[j] = b;
        m = fmaxf(m, b);
    }
    float ssum = 0.f;
    #pragma unroll
    for (int j = 0; j < Lf; j++) { v[j] = expf(v[j] - m); ssum += v[j]; }
    float inv = 1.f / ssum;
    float mm = 0.f;
    #pragma unroll
    for (int j = 0; j < Lf; j++) {
        float pj = v[j] * inv;
        float rs = g_stats[j*2 + 1], mu = g_stats[j*2];
        g_q[j*HW + p] = pj * rs;
        mm += pj * mu * rs;
    }
    g_mm[p] = mm;
}

// ---------------- hbar[c,p] ----------------
__global__ void __launch_bounds__(256) hbar_k(const float* __restrict__ xbase,
        const float* __restrict__ gg, const float* __restrict__ bb) {
    int c = blockIdx.y;
    int p = (blockIdx.x*256 + threadIdx.x) * 4;
    float4 mm4 = *reinterpret_cast<const float4*>(g_mm + p);
    float4 a = make_float4(-mm4.x, -mm4.y, -mm4.z, -mm4.w);
    #pragma unroll
    for (int j = 0; j < Lf; j++) {
        float4 xv = *reinterpret_cast<const float4*>(xbase + (size_t)j*CHW + c*HW + p);
        float4 qv = *reinterpret_cast<const float4*>(g_q + j*HW + p);
        a.x += qv.x*xv.x; a.y += qv.y*xv.y; a.z += qv.z*xv.z; a.w += qv.w*xv.w;
    }
    float4 g4 = *reinterpret_cast<const float4*>(gg + c*HW + p);
    float4 b4 = *reinterpret_cast<const float4*>(bb + c*HW + p);
    a.x = a.x*g4.x + b4.x; a.y = a.y*g4.y + b4.y;
    a.z = a.z*g4.z + b4.z; a.w = a.w*g4.w + b4.w;
    *reinterpret_cast<float4*>(g_hbar + c*HW + p) = a;
}

// ---------------- attn = Wv * hbar + bv (split into 2 channel halves; 256 blocks) ----------------
__global__ void __launch_bounds__(128) attn_gemv_k(const float* __restrict__ Wv,
                                                   const float* __restrict__ bv) {
    __shared__ __align__(16) unsigned long long Wp[Cc*16]; // Wp[c][k]=(Wv[o0+2k][c],Wv[o0+2k+1][c])
    int tid = threadIdx.x;
    int o0 = blockIdx.y * 32;
    for (int i = tid; i < Cc*16; i += 128) {
        int c = i >> 4, k = i & 15;
        Wp[c*16 + k] = pk(Wv[(o0+2*k)*Cc + c], Wv[(o0+2*k+1)*Cc + c]);
    }
    __syncthreads();
    int p = blockIdx.x*128 + tid;
    unsigned long long acc2[16];
    #pragma unroll
    for (int k = 0; k < 16; k++) acc2[k] = pk(bv[o0+2*k], bv[o0+2*k+1]);
    #pragma unroll 4
    for (int c = 0; c < Cc; c++) {
        float h = g_hbar[c*HW + p];
        unsigned long long hd = pk(h, h);
        const ulonglong2* wr = reinterpret_cast<const ulonglong2*>(&Wp[c*16]);
        #pragma unroll
        for (int k2 = 0; k2 < 8; k2++) {
            ulonglong2 w = wr[k2];
            fma2(acc2[2*k2],   w.x, hd);
            fma2(acc2[2*k2+1], w.y, hd);
        }
    }
    #pragma unroll
    for (int k = 0; k < 16; k++) {
        float lo, hi;
        upk(lo, hi, acc2[k]);
        g_attn[(o0 + 2*k)*HW + p]     = lo;
        g_attn[(o0 + 2*k + 1)*HW + p] = hi;
    }
}

// ---------------- x = xsrc + attn (all frames) + LN2 partials (fused copy for layer 0) ----------------
__global__ void addres_k(float* __restrict__ x, const float* __restrict__ xsrc) {
    int l = blockIdx.y, chunk = blockIdx.x;
    const float4* at = reinterpret_cast<const float4*>(g_attn) + chunk*2048;
    const float4* xs = reinterpret_cast<const float4*>(xsrc + (size_t)l*CHW) + chunk*2048;
    float4* xd = reinterpret_cast<float4*>(x + (size_t)l*CHW) + chunk*2048;
    float s = 0.f, s2 = 0.f;
    #pragma unroll 4
    for (int i = threadIdx.x; i < 2048; i += 256) {
        float4 v = xs[i];
        float4 a = at[i];
        v.x += a.x; v.y += a.y; v.z += a.z; v.w += a.w;
        xd[i] = v;
        s  += v.x + v.y + v.z + v.w;
        s2 += v.x*v.x + v.y*v.y + v.z*v.z + v.w*v.w;
    }
    reduce_write(s, s2, l, chunk);
}

// ---------------- tensor-core FFN (tf32 mma.sync), 2 CTAs/SM ----------------
#define FFN_SMEM (26112*4)

__global__ void __launch_bounds__(256, 2) ffn_k(float* __restrict__ x,
        const float* __restrict__ gg, const float* __restrict__ bb,
        const float* __restrict__ W1, const float* __restrict__ b1,
        const float* __restrict__ W2, const float* __restrict__ b2) {
    extern __shared__ __align__(16) float smf[];
    unsigned* hsu = reinterpret_cast<unsigned*>(smf);
    unsigned* w1u = reinterpret_cast<unsigned*>(smf + 8704);
    unsigned* f1u = reinterpret_cast<unsigned*>(smf);          // phase2 alias of A
    unsigned* w2u = reinterpret_cast<unsigned*>(smf + 17408);  // region B
    float*    ob  = smf + 17408;                                // phase3 alias of B
    __shared__ float b1s[128];
    __shared__ float b2s[64];

    int tid = threadIdx.x;
    int l = blockIdx.y;
    int p0 = blockIdx.x * 128;
    float mu = g_stats[l*2], rs = g_stats[l*2 + 1];
    float* xl = x + (size_t)l*CHW;

    if (tid < 128) b1s[tid] = b1[tid];
    if (tid < 64)  b2s[tid] = b2[tid];

    for (int i = tid; i < 2048; i += 256) {
        int c = i >> 5, px4 = (i & 31) * 4;
        int off = c*HW + p0 + px4;
        float4 xv = *reinterpret_cast<const float4*>(xl + off);
        float4 g4 = *reinterpret_cast<const float4*>(gg + off);
        float4 b4 = *reinterpret_cast<const float4*>(bb + off);
        float hv[4];
        hv[0] = (xv.x - mu)*rs*g4.x + b4.x;
        hv[1] = (xv.y - mu)*rs*g4.y + b4.y;
        hv[2] = (xv.z - mu)*rs*g4.z + b4.z;
        hv[3] = (xv.w - mu)*rs*g4.w + b4.w;
        #pragma unroll
        for (int u = 0; u < 4; u++)
            hsu[(px4+u)*68 + c] = tf32c(hv[u]);
    }
    for (int i = tid; i < 2048; i += 256) {
        int o = i >> 4, c4 = (i & 15) * 4;
        float4 w4 = *reinterpret_cast<const float4*>(W1 + o*64 + c4);
        uint4 t;
        t.x = tf32c(w4.x); t.y = tf32c(w4.y); t.z = tf32c(w4.z); t.w = tf32c(w4.w);
        *reinterpret_cast<uint4*>(w1u + o*68 + c4) = t;
    }
    for (int i = tid; i < 2048; i += 256) {
        int c = i >> 5, o4 = (i & 31) * 4;
        float4 w4 = *reinterpret_cast<const float4*>(W2 + c*128 + o4);
        uint4 t;
        t.x = tf32c(w4.x); t.y = tf32c(w4.y); t.z = tf32c(w4.z); t.w = tf32c(w4.w);
        *reinterpret_cast<uint4*>(w2u + c*132 + o4) = t;
    }
    __syncthreads();

    int lane = tid & 31, warp = tid >> 5;
    int gid = lane >> 2, tig = lane & 3;
    int m0 = warp * 16;

    float d[16][4];
    #pragma unroll
    for (int nt = 0; nt < 16; nt++) { d[nt][0]=0.f; d[nt][1]=0.f; d[nt][2]=0.f; d[nt][3]=0.f; }
    #pragma unroll
    for (int kt = 0; kt < 8; kt++) {
        int ka = kt*8 + tig;
        unsigned a0 = hsu[(m0+gid)*68 + ka];
        unsigned a1 = hsu[(m0+gid+8)*68 + ka];
        unsigned a2 = hsu[(m0+gid)*68 + ka + 4];
        unsigned a3 = hsu[(m0+gid+8)*68 + ka + 4];
        #pragma unroll
        for (int nt = 0; nt < 16; nt++) {
            unsigned b0 = w1u[(nt*8+gid)*68 + ka];
            unsigned b1f = w1u[(nt*8+gid)*68 + ka + 4];
            mma_tf32(d[nt][0], d[nt][1], d[nt][2], d[nt][3], a0, a1, a2, a3, b0, b1f);
        }
    }
    __syncthreads();

    #pragma unroll
    for (int nt = 0; nt < 16; nt++) {
        int col = nt*8 + 2*tig;
        float v0 = d[nt][0] + b1s[col];
        float v1 = d[nt][1] + b1s[col+1];
        float v2 = d[nt][2] + b1s[col];
        float v3 = d[nt][3] + b1s[col+1];
        v0 = v0 > 0.f ? v0 : 0.01f*v0;
        v1 = v1 > 0.f ? v1 : 0.01f*v1;
        v2 = v2 > 0.f ? v2 : 0.01f*v2;
        v3 = v3 > 0.f ? v3 : 0.01f*v3;
        uint2 lo; lo.x = tf32c(v0); lo.y = tf32c(v1);
        uint2 hi; hi.x = tf32c(v2); hi.y = tf32c(v3);
        *reinterpret_cast<uint2*>(f1u + (m0+gid)*132 + col)   = lo;
        *reinterpret_cast<uint2*>(f1u + (m0+gid+8)*132 + col) = hi;
    }
    __syncthreads();

    float e[8][4];
    #pragma unroll
    for (int nt = 0; nt < 8; nt++) { e[nt][0]=0.f; e[nt][1]=0.f; e[nt][2]=0.f; e[nt][3]=0.f; }
    #pragma unroll
    for (int kt = 0; kt < 16; kt++) {
        int ka = kt*8 + tig;
        unsigned a0 = f1u[(m0+gid)*132 + ka];
        unsigned a1 = f1u[(m0+gid+8)*132 + ka];
        unsigned a2 = f1u[(m0+gid)*132 + ka + 4];
        unsigned a3 = f1u[(m0+gid+8)*132 + ka + 4];
        #pragma unroll
        for (int nt = 0; nt < 8; nt++) {
            unsigned b0 = w2u[(nt*8+gid)*132 + ka];
            unsigned b1f = w2u[(nt*8+gid)*132 + ka + 4];
            mma_tf32(e[nt][0], e[nt][1], e[nt][2], e[nt][3], a0, a1, a2, a3, b0, b1f);
        }
    }
    __syncthreads();

    #pragma unroll
    for (int nt = 0; nt < 8; nt++) {
        int col = nt*8 + 2*tig;
        float2 lo, hi;
        lo.x = e[nt][0] + b2s[col];
        lo.y = e[nt][1] + b2s[col+1];
        hi.x = e[nt][2] + b2s[col];
        hi.y = e[nt][3] + b2s[col+1];
        *reinterpret_cast<float2*>(ob + (m0+gid)*68 + col)   = lo;
        *reinterpret_cast<float2*>(ob + (m0+gid+8)*68 + col) = hi;
    }
    __syncthreads();

    {
        int px = tid & 127;
        int ch0 = (tid >> 7) * 32;
        float s = 0.f, s2 = 0.f;
        #pragma unroll 4
        for (int c = ch0; c < ch0 + 32; c++) {
            int off = c*HW + p0 + px;
            float v = xl[off] + ob[px*68 + c];
            xl[off] = v;
            s += v;
            s2 += v*v;
        }
        reduce_write(s, s2, l, blockIdx.x);
    }
}

// ---------------- launch ----------------
extern "C" void kernel_launch(void* const* d_in, const int* in_sizes, int n_in,
                              void* d_out, int out_size) {
    const float* x_in = (const float*)d_in[0];
    const float* ln1g = (const float*)d_in[1];
    const float* ln1b = (const float*)d_in[2];
    // d_in[3]=Wq, d_in[4]=bq, d_in[10]=ba: dead (softmax over j cancels them)
    const float* Wk   = (const float*)d_in[5];
    const float* bk   = (const float*)d_in[6];
    const float* Wv   = (const float*)d_in[7];
    const float* bv   = (const float*)d_in[8];
    const float* Wa   = (const float*)d_in[9];
    const float* ln2g = (const float*)d_in[11];
    const float* ln2b = (const float*)d_in[12];
    const float* W1   = (const float*)d_in[13];
    const float* b1   = (const float*)d_in[14];
    const float* W2   = (const float*)d_in[15];
    const float* b2   = (const float*)d_in[16];
    float* x = (float*)d_out;

    cudaFuncSetAttribute(ffn_k, cudaFuncAttributeMaxDynamicSharedMemorySize, FFN_SMEM);

    stats_k<<<dim3(128, Lf), 256>>>(x_in);   // layer-0 LN1 partials, no copy

    for (int d = 0; d < 4; d++) {
        const float* xbase = (d == 0) ? x_in : x;   // attention path reads pre-residual tensor
        ln_final_k<<<1, 512>>>(Wa + (size_t)d*2*Cc*25, Wk + (size_t)d*Cc*Cc,
                               bk + (size_t)d*Cc, 1, 128);
        conv_b_k<<<dim3(8, Hh/8, Lf), 256>>>(xbase, ln1g + (size_t)d*CHW, ln1b + (size_t)d*CHW);
        softmax_k<<<HW/256, 256>>>();
        hbar_k<<<dim3(HW/1024, Cc), 256>>>(xbase, ln1g + (size_t)d*CHW, ln1b + (size_t)d*CHW);
        attn_gemv_k<<<dim3(HW/128, 2), 128>>>(Wv + (size_t)d*Cc*Cc, bv + (size_t)d*Cc);
        addres_k<<<dim3(128, Lf), 256>>>(x, xbase);
        ln_final_k<<<1, 512>>>(Wa, Wk, bk, 0, 128);
        ffn_k<<<dim3(HW/128, Lf), 256, FFN_SMEM>>>(x, ln2g + (size_t)d*CHW, ln2b + (size_t)d*CHW,
                                                   W1 + (size_t)d*2*Cc*Cc, b1 + (size_t)d*2*Cc,
                                                   W2 + (size_t)d*Cc*2*Cc, b2 + (size_t)d*Cc);
    }
}